// round 4
// baseline (speedup 1.0000x reference)
#include <cuda_runtime.h>
#include <stdint.h>

// Problem constants (fixed by the dataset problem).
#define HH 112
#define WW 112
#define MAXB 4   // scratch sized for up to 4 batches

// Per-pixel, per-channel winner key:
//   high 32 = order-preserving encoded flat depth
//   low  32 = raw float bits of that triangle's flat color for this channel
// atomicMax picks the max-depth triangle; the payload rides along. Ties between
// bit-equal depths of distinct triangles resolve by color bits instead of lowest
// index (duplicated triangles have identical colors, so this is benign).
// 0 means "uncovered" (fenc of any finite depth is nonzero). Zero-initialized at
// module load; phase B re-zeros after consuming (invariant across graph replays).
__device__ unsigned long long g_keys[MAXB * HH * WW * 3];

// Software grid barrier state (all blocks resident: grid <= 148 SMs).
__device__ unsigned int g_count = 0;
__device__ unsigned int g_gen   = 0;

__device__ __forceinline__ unsigned int fenc(float f) {
    unsigned int u = __float_as_uint(f);
    return (u & 0x80000000u) ? ~u : (u | 0x80000000u);
}

__global__ void __launch_bounds__(256, 1)
fused_raster(const float* __restrict__ vertices,
             const float* __restrict__ colors,
             const int*   __restrict__ triangles,
             float* __restrict__ out,
             int B, int ntri, int nver, int nblocks) {
    const int tid   = blockIdx.x * blockDim.x + threadIdx.x;
    const int nwork = B * ntri;

    // ---------------- Phase A: scatter raster (depth|color payload) --------
    if (tid < nwork) {
        int b = tid / ntri;
        int t = tid - b * ntri;

        // One L2 trip: 3 independent index loads.
        int i0 = __ldg(&triangles[t]);
        int i1 = __ldg(&triangles[ntri + t]);
        int i2 = __ldg(&triangles[2 * ntri + t]);

        // One L2 trip: 9 vertex + 9 color loads, all independent once idx ready.
        const float* V = vertices + (size_t)b * 3 * nver;
        const float* C = colors   + (size_t)b * 3 * nver;
        float x0 = __ldg(&V[i0]),            x1 = __ldg(&V[i1]),            x2 = __ldg(&V[i2]);
        float y0 = __ldg(&V[nver + i0]),     y1 = __ldg(&V[nver + i1]),     y2 = __ldg(&V[nver + i2]);
        float z0 = __ldg(&V[2 * nver + i0]), z1 = __ldg(&V[2 * nver + i1]), z2 = __ldg(&V[2 * nver + i2]);
        float r0 = __ldg(&C[i0]),            r1 = __ldg(&C[i1]),            r2 = __ldg(&C[i2]);
        float g0 = __ldg(&C[nver + i0]),     g1 = __ldg(&C[nver + i1]),     g2 = __ldg(&C[nver + i2]);
        float b0 = __ldg(&C[2 * nver + i0]), b1 = __ldg(&C[2 * nver + i1]), b2 = __ldg(&C[2 * nver + i2]);

        float depth = ((z0 + z1) + z2) / 3.0f;
        float cr = ((r0 + r1) + r2) / 3.0f;
        float cg = ((g0 + g1) + g2) / 3.0f;
        float cb = ((b0 + b1) + b2) / 3.0f;

        float xmin = fminf(fminf(x0, x1), x2);
        float xmax = fmaxf(fmaxf(x0, x1), x2);
        float ymin = fminf(fminf(y0, y1), y2);
        float ymax = fmaxf(fmaxf(y0, y1), y2);

        // Match reference: max(ceil(min),0), min(floor(max), dim-1) in float, then cast.
        int umin = (int)fmaxf(ceilf(xmin), 0.0f);
        int umax = (int)fminf(floorf(xmax), (float)(WW - 1));
        int vmin = (int)fmaxf(ceilf(ymin), 0.0f);
        int vmax = (int)fminf(floorf(ymax), (float)(HH - 1));

        if (umin <= umax && vmin <= vmax) {
            unsigned long long dhi = (unsigned long long)fenc(depth) << 32;
            unsigned long long kr = dhi | __float_as_uint(cr);
            unsigned long long kg = dhi | __float_as_uint(cg);
            unsigned long long kb = dhi | __float_as_uint(cb);
            unsigned long long* base = g_keys + (size_t)b * HH * WW * 3;
            for (int v = vmin; v <= vmax; ++v) {
                unsigned long long* row = base + (size_t)v * (WW * 3);
                for (int u = umin; u <= umax; ++u) {
                    atomicMax(&row[u * 3 + 0], kr);
                    atomicMax(&row[u * 3 + 1], kg);
                    atomicMax(&row[u * 3 + 2], kb);
                }
            }
        }
    }

    // ---------------- Grid barrier (load-poll, epoch-based, wrap-safe) ------
    __syncthreads();
    if (threadIdx.x == 0) {
        volatile unsigned int* vgen = &g_gen;
        unsigned int my_gen = *vgen;                   // read BEFORE arriving
        __threadfence();                               // order phase-A atomics
        unsigned int ticket = atomicAdd(&g_count, 1u);
        if (ticket == (unsigned int)nblocks - 1u) {
            g_count = 0u;                              // all arrived; reset for next replay
            __threadfence();
            atomicAdd(&g_gen, 1u);                     // release
        } else {
            while (*vgen == my_gen) { __nanosleep(32); }
        }
        __threadfence();
    }
    __syncthreads();

    // ---------------- Phase B: resolve + reset (ONE dependent L2 trip) ------
    const int npix = B * HH * WW;
    if (tid < npix) {
        int b   = tid / (HH * WW);
        int pix = tid - b * (HH * WW);

        unsigned long long* slot = g_keys + ((size_t)b * HH * WW + pix) * 3;
        unsigned long long kr = __ldcg(&slot[0]);      // 3 independent L2 loads
        unsigned long long kg = __ldcg(&slot[1]);
        unsigned long long kb = __ldcg(&slot[2]);
        slot[0] = 0ull;                                // restore invariant
        slot[1] = 0ull;
        slot[2] = 0ull;

        float mask = 0.0f, c0 = 0.0f, c1 = 0.0f, c2 = 0.0f;
        if (kr != 0ull) {
            mask = 1.0f;
            c0 = __uint_as_float((unsigned int)(kr & 0xffffffffu));
            c1 = __uint_as_float((unsigned int)(kg & 0xffffffffu));
            c2 = __uint_as_float((unsigned int)(kb & 0xffffffffu));
        }

        // Output layout: face_mask [B,1,H,W] then image [B,3,H,W], flattened.
        out[(size_t)b * HH * WW + pix] = mask;
        float* img = out + (size_t)B * HH * WW;
        img[((size_t)b * 3 + 0) * HH * WW + pix] = c0;
        img[((size_t)b * 3 + 1) * HH * WW + pix] = c1;
        img[((size_t)b * 3 + 2) * HH * WW + pix] = c2;
    }
}

extern "C" void kernel_launch(void* const* d_in, const int* in_sizes, int n_in,
                              void* d_out, int out_size) {
    const float* vertices  = (const float*)d_in[0];
    const float* colors    = (const float*)d_in[1];
    const int*   triangles = (const int*)d_in[2];

    int ntri = in_sizes[2] / 3;
    int B    = out_size / (4 * HH * WW);
    int nver = in_sizes[0] / (3 * B);
    float* out = (float*)d_out;

    int npix    = B * HH * WW;                      // 25088 for B=2
    int threads = 256;
    int nblocks = (npix + threads - 1) / threads;   // 98 blocks < 148 SMs: all resident

    fused_raster<<<nblocks, threads>>>(vertices, colors, triangles, out,
                                       B, ntri, nver, nblocks);
}

// round 5
// speedup vs baseline: 1.1510x; 1.1510x over previous
#include <cuda_runtime.h>
#include <stdint.h>

// Problem constants (fixed by the dataset problem).
#define HH 112
#define WW 112
#define MAXB 4   // scratch sized for up to 4 batches

// Per-pixel, per-channel winner key:
//   high 32 = order-preserving encoded flat depth
//   low  32 = raw float bits of that triangle's flat color for this channel
// atomicMax (no return -> REDG) picks the max-depth triangle; payload rides
// along. Ties between bit-equal depths of distinct triangles resolve by color
// bits instead of lowest index (duplicate triangles carry identical colors, so
// this is benign; distinct-triangle exact ties are measure-zero).
// 0 means "uncovered". Zero-initialized at module load; resolve re-zeros after
// consuming, so the invariant holds across graph replays — no init kernel.
__device__ unsigned long long g_keys[MAXB * HH * WW * 3];

__device__ __forceinline__ unsigned int fenc(float f) {
    unsigned int u = __float_as_uint(f);
    return (u & 0x80000000u) ? ~u : (u | 0x80000000u);
}

__global__ void __launch_bounds__(128)
raster_kernel(const float* __restrict__ vertices,
              const float* __restrict__ colors,
              const int*   __restrict__ triangles,
              int B, int ntri, int nver) {
    int idx = blockIdx.x * blockDim.x + threadIdx.x;
    if (idx >= B * ntri) return;
    int b = idx / ntri;
    int t = idx - b * ntri;

    // First L2 trip: 3 independent index loads.
    int i0 = __ldg(&triangles[t]);
    int i1 = __ldg(&triangles[ntri + t]);
    int i2 = __ldg(&triangles[2 * ntri + t]);

    // Second L2 trip: 18 independent loads once indices land.
    const float* V = vertices + (size_t)b * 3 * nver;
    const float* C = colors   + (size_t)b * 3 * nver;
    float x0 = __ldg(&V[i0]),            x1 = __ldg(&V[i1]),            x2 = __ldg(&V[i2]);
    float y0 = __ldg(&V[nver + i0]),     y1 = __ldg(&V[nver + i1]),     y2 = __ldg(&V[nver + i2]);
    float z0 = __ldg(&V[2 * nver + i0]), z1 = __ldg(&V[2 * nver + i1]), z2 = __ldg(&V[2 * nver + i2]);
    float r0 = __ldg(&C[i0]),            r1 = __ldg(&C[i1]),            r2 = __ldg(&C[i2]);
    float g0 = __ldg(&C[nver + i0]),     g1 = __ldg(&C[nver + i1]),     g2 = __ldg(&C[nver + i2]);
    float b0 = __ldg(&C[2 * nver + i0]), b1 = __ldg(&C[2 * nver + i1]), b2 = __ldg(&C[2 * nver + i2]);

    float depth = ((z0 + z1) + z2) / 3.0f;
    float cr = ((r0 + r1) + r2) / 3.0f;
    float cg = ((g0 + g1) + g2) / 3.0f;
    float cb = ((b0 + b1) + b2) / 3.0f;

    float xmin = fminf(fminf(x0, x1), x2);
    float xmax = fmaxf(fmaxf(x0, x1), x2);
    float ymin = fminf(fminf(y0, y1), y2);
    float ymax = fmaxf(fmaxf(y0, y1), y2);

    // Match reference: max(ceil(min),0), min(floor(max), dim-1) in float, then cast.
    int umin = (int)fmaxf(ceilf(xmin), 0.0f);
    int umax = (int)fminf(floorf(xmax), (float)(WW - 1));
    int vmin = (int)fmaxf(ceilf(ymin), 0.0f);
    int vmax = (int)fminf(floorf(ymax), (float)(HH - 1));
    if (umin > umax || vmin > vmax) return;

    unsigned long long dhi = (unsigned long long)fenc(depth) << 32;
    unsigned long long kr = dhi | __float_as_uint(cr);
    unsigned long long kg = dhi | __float_as_uint(cg);
    unsigned long long kb = dhi | __float_as_uint(cb);

    unsigned long long* base = g_keys + (size_t)b * HH * WW * 3;
    for (int v = vmin; v <= vmax; ++v) {
        unsigned long long* row = base + (size_t)v * (WW * 3);
        for (int u = umin; u <= umax; ++u) {
            // Return value discarded -> REDG (fire-and-forget, nothing stalls).
            atomicMax(&row[u * 3 + 0], kr);
            atomicMax(&row[u * 3 + 1], kg);
            atomicMax(&row[u * 3 + 2], kb);
        }
    }
}

__global__ void __launch_bounds__(256)
resolve_kernel(float* __restrict__ out, int B) {
    int tid  = blockIdx.x * blockDim.x + threadIdx.x;
    int npix = B * HH * WW;
    if (tid >= npix) return;
    int b   = tid / (HH * WW);
    int pix = tid - b * (HH * WW);

    unsigned long long* slot = g_keys + (size_t)tid * 3;
    unsigned long long kr = __ldcg(&slot[0]);   // 3 independent L2 loads
    unsigned long long kg = __ldcg(&slot[1]);
    unsigned long long kb = __ldcg(&slot[2]);
    slot[0] = 0ull;                             // restore invariant for next replay
    slot[1] = 0ull;
    slot[2] = 0ull;

    float mask = 0.0f, c0 = 0.0f, c1 = 0.0f, c2 = 0.0f;
    if (kr != 0ull) {
        mask = 1.0f;
        c0 = __uint_as_float((unsigned int)(kr & 0xffffffffu));
        c1 = __uint_as_float((unsigned int)(kg & 0xffffffffu));
        c2 = __uint_as_float((unsigned int)(kb & 0xffffffffu));
    }

    // Output layout: face_mask [B,1,H,W] then image [B,3,H,W], flattened.
    out[(size_t)b * HH * WW + pix] = mask;
    float* img = out + (size_t)B * HH * WW;
    img[((size_t)b * 3 + 0) * HH * WW + pix] = c0;
    img[((size_t)b * 3 + 1) * HH * WW + pix] = c1;
    img[((size_t)b * 3 + 2) * HH * WW + pix] = c2;
}

extern "C" void kernel_launch(void* const* d_in, const int* in_sizes, int n_in,
                              void* d_out, int out_size) {
    const float* vertices  = (const float*)d_in[0];
    const float* colors    = (const float*)d_in[1];
    const int*   triangles = (const int*)d_in[2];

    int ntri = in_sizes[2] / 3;
    int B    = out_size / (4 * HH * WW);
    int nver = in_sizes[0] / (3 * B);
    float* out = (float*)d_out;

    int nwork = B * ntri;
    raster_kernel<<<(nwork + 127) / 128, 128>>>(vertices, colors, triangles,
                                                B, ntri, nver);

    int npix = B * HH * WW;
    resolve_kernel<<<(npix + 255) / 256, 256>>>(out, B);
}